// round 6
// baseline (speedup 1.0000x reference)
#include <cuda_runtime.h>
#include <math.h>
#include <float.h>

#define T_ 1024
#define B_ 8
#define E_ 512
#define H_ 8
#define D_ 64
#define S_ 2048

// ---------------- scratch (device globals; no allocations) ----------------
__device__ float g_qin[T_ * B_ * E_];                 // (t,b,e)            16 MB
__device__ float g_q[B_ * H_ * T_ * D_];              // (b,h,t,d)          16 MB
__device__ float g_k[B_ * H_ * S_ * D_];              // (b,h,s,d)          33 MB
__device__ float g_v[B_ * H_ * S_ * D_];              // (b,h,s,d)          33 MB
__device__ float g_p[(size_t)B_ * H_ * T_ * S_];      // (b,h,t,s)         512 MB
__device__ float g_attn[T_ * B_ * E_];                // (t,b, h*64+d)      16 MB

// ---------------- q_in = shift(fwd,+1) + shift(bwd,-1) ----------------
__global__ void build_qin_kernel(const float* __restrict__ fwd,
                                 const float* __restrict__ bwd) {
    int idx = blockIdx.x * blockDim.x + threadIdx.x;   // over T*B*E, layout (t,b,e)
    int tb = idx / E_;
    int t = tb / B_;
    float v = 0.f;
    if (t > 0)      v += fwd[idx - B_ * E_];
    if (t < T_ - 1) v += bwd[idx + B_ * E_];
    g_qin[idx] = v;
}

// ---------------- tiled GEMM helpers (BM=BN=64, BK=16, 256 thr, 4x4 micro) ----------------
// C = A(MxK) * W(NxK)^T + bias ; A,W row-major.

__global__ void proj_q_kernel(const float* __restrict__ W,
                              const float* __restrict__ bias) {
    __shared__ float As[16][68];
    __shared__ float Bs[16][68];
    const int tid = threadIdx.x;
    const int row0 = blockIdx.y * 64;   // rows of (t*B+b), M=8192
    const int col0 = blockIdx.x * 64;   // f in [0,512)
    float acc[4][4] = {};
    const int r0 = (tid >> 4) << 2, c0 = (tid & 15) << 2;
    for (int k0 = 0; k0 < E_; k0 += 16) {
        #pragma unroll
        for (int i = 0; i < 4; i++) {
            int idx = tid + i * 256;
            int r = idx >> 4, c = idx & 15;
            As[c][r] = g_qin[(row0 + r) * E_ + k0 + c];
            Bs[c][r] = W[(col0 + r) * E_ + k0 + c];
        }
        __syncthreads();
        #pragma unroll
        for (int k = 0; k < 16; k++) {
            float a0 = As[k][r0], a1 = As[k][r0+1], a2 = As[k][r0+2], a3 = As[k][r0+3];
            float b0 = Bs[k][c0], b1 = Bs[k][c0+1], b2 = Bs[k][c0+2], b3 = Bs[k][c0+3];
            acc[0][0] += a0*b0; acc[0][1] += a0*b1; acc[0][2] += a0*b2; acc[0][3] += a0*b3;
            acc[1][0] += a1*b0; acc[1][1] += a1*b1; acc[1][2] += a1*b2; acc[1][3] += a1*b3;
            acc[2][0] += a2*b0; acc[2][1] += a2*b1; acc[2][2] += a2*b2; acc[2][3] += a2*b3;
            acc[3][0] += a3*b0; acc[3][1] += a3*b1; acc[3][2] += a3*b2; acc[3][3] += a3*b3;
        }
        __syncthreads();
    }
    #pragma unroll
    for (int i = 0; i < 4; i++) {
        int r = row0 + r0 + i;
        int t = r >> 3, b = r & 7;
        #pragma unroll
        for (int j = 0; j < 4; j++) {
            int f = col0 + c0 + j;
            int h = f >> 6, d = f & 63;
            g_q[(((b << 3) + h) * T_ + t) * D_ + d] = acc[i][j] + bias[f];
        }
    }
}

__global__ void proj_kv_kernel(const float* __restrict__ fwd,
                               const float* __restrict__ bwd,
                               const float* __restrict__ W,
                               const float* __restrict__ bias) {
    __shared__ float As[16][68];
    __shared__ float Bs[16][68];
    const int tid = threadIdx.x;
    const int row0 = blockIdx.y * 64;   // rows of kv_in (s*B+b), M=16384
    const int col0 = blockIdx.x * 64;   // f in [0,1024): [0,512)=K, [512,1024)=V
    const float* Asrc = (row0 < T_ * B_) ? (fwd + (size_t)row0 * E_)
                                         : (bwd + (size_t)(row0 - T_ * B_) * E_);
    float acc[4][4] = {};
    const int r0 = (tid >> 4) << 2, c0 = (tid & 15) << 2;
    for (int k0 = 0; k0 < E_; k0 += 16) {
        #pragma unroll
        for (int i = 0; i < 4; i++) {
            int idx = tid + i * 256;
            int r = idx >> 4, c = idx & 15;
            As[c][r] = Asrc[r * E_ + k0 + c];
            Bs[c][r] = W[(size_t)(E_ + col0 + r) * E_ + k0 + c];
        }
        __syncthreads();
        #pragma unroll
        for (int k = 0; k < 16; k++) {
            float a0 = As[k][r0], a1 = As[k][r0+1], a2 = As[k][r0+2], a3 = As[k][r0+3];
            float b0 = Bs[k][c0], b1 = Bs[k][c0+1], b2 = Bs[k][c0+2], b3 = Bs[k][c0+3];
            acc[0][0] += a0*b0; acc[0][1] += a0*b1; acc[0][2] += a0*b2; acc[0][3] += a0*b3;
            acc[1][0] += a1*b0; acc[1][1] += a1*b1; acc[1][2] += a1*b2; acc[1][3] += a1*b3;
            acc[2][0] += a2*b0; acc[2][1] += a2*b1; acc[2][2] += a2*b2; acc[2][3] += a2*b3;
            acc[3][0] += a3*b0; acc[3][1] += a3*b1; acc[3][2] += a3*b2; acc[3][3] += a3*b3;
        }
        __syncthreads();
    }
    #pragma unroll
    for (int i = 0; i < 4; i++) {
        int r = row0 + r0 + i;
        int s = r >> 3, b = r & 7;
        #pragma unroll
        for (int j = 0; j < 4; j++) {
            int f = col0 + c0 + j;
            float val = acc[i][j] + bias[E_ + f];
            if (f < E_) {
                int h = f >> 6, d = f & 63;
                g_k[(((size_t)((b << 3) + h)) * S_ + s) * D_ + d] = val;
            } else {
                int f2 = f - E_;
                int h = f2 >> 6, d = f2 & 63;
                g_v[(((size_t)((b << 3) + h)) * S_ + s) * D_ + d] = val;
            }
        }
    }
}

// ---------------- scores: p[bh,t,s] = q . k, masked ----------------
__global__ void scores_kernel(const int* __restrict__ kpm) {
    __shared__ float Qs[64][68];
    __shared__ float Ks[64][68];
    const int bh = blockIdx.z;
    const int b = bh >> 3;
    const int t0 = blockIdx.y * 64;
    const int s0 = blockIdx.x * 64;
    const float* Q = g_q + (size_t)bh * T_ * D_;
    const float* K = g_k + (size_t)bh * S_ * D_;
    const int tid = threadIdx.x;
    #pragma unroll
    for (int i = 0; i < 16; i++) {
        int idx = tid + i * 256;
        int r = idx >> 6, d = idx & 63;
        Qs[d][r] = Q[(t0 + r) * D_ + d];
        Ks[d][r] = K[(s0 + r) * D_ + d];
    }
    __syncthreads();
    const int r0 = (tid >> 4) << 2, c0 = (tid & 15) << 2;
    float acc[4][4] = {};
    #pragma unroll
    for (int k = 0; k < 64; k++) {
        float a0 = Qs[k][r0], a1 = Qs[k][r0+1], a2 = Qs[k][r0+2], a3 = Qs[k][r0+3];
        float b0 = Ks[k][c0], b1 = Ks[k][c0+1], b2 = Ks[k][c0+2], b3 = Ks[k][c0+3];
        acc[0][0] += a0*b0; acc[0][1] += a0*b1; acc[0][2] += a0*b2; acc[0][3] += a0*b3;
        acc[1][0] += a1*b0; acc[1][1] += a1*b1; acc[1][2] += a1*b2; acc[1][3] += a1*b3;
        acc[2][0] += a2*b0; acc[2][1] += a2*b1; acc[2][2] += a2*b2; acc[2][3] += a2*b3;
        acc[3][0] += a3*b0; acc[3][1] += a3*b1; acc[3][2] += a3*b2; acc[3][3] += a3*b3;
    }
    float* Prow = g_p + (size_t)bh * T_ * S_;
    #pragma unroll
    for (int i = 0; i < 4; i++) {
        int t = t0 + r0 + i;
        #pragma unroll
        for (int j = 0; j < 4; j++) {
            int s = s0 + c0 + j;
            bool allowed = (s < t) || (s > t + T_);
            bool pad = kpm[b * T_ + (s & (T_ - 1))] != 0;
            float val = (allowed && !pad) ? acc[i][j] : -1e30f;
            Prow[(size_t)t * S_ + s] = val;
        }
    }
}

// ---------------- softmax per (b,t) over all heads + head-mean ----------------
__device__ __forceinline__ float blk_reduce(float v, bool is_max, float* red) {
    #pragma unroll
    for (int o = 16; o; o >>= 1) {
        float w = __shfl_xor_sync(0xffffffffu, v, o);
        v = is_max ? fmaxf(v, w) : v + w;
    }
    if ((threadIdx.x & 31) == 0) red[threadIdx.x >> 5] = v;
    __syncthreads();
    if (threadIdx.x < 32) {
        float x = (threadIdx.x < 8) ? red[threadIdx.x] : (is_max ? -INFINITY : 0.f);
        #pragma unroll
        for (int o = 4; o; o >>= 1) {
            float w = __shfl_xor_sync(0xffffffffu, x, o);
            x = is_max ? fmaxf(x, w) : x + w;
        }
        if (threadIdx.x == 0) red[0] = x;
    }
    __syncthreads();
    float r = red[0];
    __syncthreads();
    return r;
}

__global__ void softmax_avg_kernel(float* __restrict__ avg_out) {
    __shared__ float red[32];
    const int bt = blockIdx.x;          // b*T + t
    const int b = bt >> 10;
    const int t = bt & (T_ - 1);
    const int tid = threadIdx.x;
    float avg[8] = {};
    for (int h = 0; h < H_; h++) {
        float* row = g_p + ((size_t)(((b << 3) + h) * T_ + t)) * S_;
        float vreg[8];
        float m = -INFINITY;
        #pragma unroll
        for (int i = 0; i < 8; i++) {
            vreg[i] = row[tid + (i << 8)];
            m = fmaxf(m, vreg[i]);
        }
        m = blk_reduce(m, true, red);
        float sum = 0.f;
        #pragma unroll
        for (int i = 0; i < 8; i++) {
            vreg[i] = expf(vreg[i] - m);
            sum += vreg[i];
        }
        sum = blk_reduce(sum, false, red);
        float inv = 1.f / sum;
        #pragma unroll
        for (int i = 0; i < 8; i++) {
            float p = vreg[i] * inv;
            row[tid + (i << 8)] = p;
            avg[i] += p;
        }
    }
    size_t o = (size_t)bt * S_;
    #pragma unroll
    for (int i = 0; i < 8; i++)
        avg_out[o + tid + (i << 8)] = avg[i] * (1.f / (float)H_);
}

// ---------------- attn = p @ v ----------------
__global__ void attn_kernel() {
    __shared__ float Ps[16][68];
    __shared__ float Vs[16][64];
    const int bh = blockIdx.z;
    const int t0 = blockIdx.y * 64;
    const float* P = g_p + (size_t)bh * T_ * S_ + (size_t)t0 * S_;
    const float* V = g_v + (size_t)bh * S_ * D_;
    const int tid = threadIdx.x;
    const int r0 = (tid >> 4) << 2, c0 = (tid & 15) << 2;
    float acc[4][4] = {};
    for (int s0 = 0; s0 < S_; s0 += 16) {
        #pragma unroll
        for (int i = 0; i < 4; i++) {
            int idx = tid + i * 256;
            int r = idx >> 4, c = idx & 15;
            Ps[c][r] = P[(size_t)r * S_ + s0 + c];
            int k = idx >> 6, n = idx & 63;
            Vs[k][n] = V[(s0 + k) * D_ + n];
        }
        __syncthreads();
        #pragma unroll
        for (int k = 0; k < 16; k++) {
            float a0 = Ps[k][r0], a1 = Ps[k][r0+1], a2 = Ps[k][r0+2], a3 = Ps[k][r0+3];
            float b0 = Vs[k][c0], b1 = Vs[k][c0+1], b2 = Vs[k][c0+2], b3 = Vs[k][c0+3];
            acc[0][0] += a0*b0; acc[0][1] += a0*b1; acc[0][2] += a0*b2; acc[0][3] += a0*b3;
            acc[1][0] += a1*b0; acc[1][1] += a1*b1; acc[1][2] += a1*b2; acc[1][3] += a1*b3;
            acc[2][0] += a2*b0; acc[2][1] += a2*b1; acc[2][2] += a2*b2; acc[2][3] += a2*b3;
            acc[3][0] += a3*b0; acc[3][1] += a3*b1; acc[3][2] += a3*b2; acc[3][3] += a3*b3;
        }
        __syncthreads();
    }
    const int b = bh >> 3, h = bh & 7;
    #pragma unroll
    for (int i = 0; i < 4; i++) {
        int t = t0 + r0 + i;
        #pragma unroll
        for (int j = 0; j < 4; j++) {
            int d = c0 + j;
            g_attn[((t << 3) + b) * E_ + (h << 6) + d] = acc[i][j];
        }
    }
}

// ---------------- out = attn @ out_w^T + out_b ----------------
__global__ void out_proj_kernel(const float* __restrict__ W,
                                const float* __restrict__ bias,
                                float* __restrict__ out) {
    __shared__ float As[16][68];
    __shared__ float Bs[16][68];
    const int tid = threadIdx.x;
    const int row0 = blockIdx.y * 64;
    const int col0 = blockIdx.x * 64;
    float acc[4][4] = {};
    const int r0 = (tid >> 4) << 2, c0 = (tid & 15) << 2;
    for (int k0 = 0; k0 < E_; k0 += 16) {
        #pragma unroll
        for (int i = 0; i < 4; i++) {
            int idx = tid + i * 256;
            int r = idx >> 4, c = idx & 15;
            As[c][r] = g_attn[(row0 + r) * E_ + k0 + c];
            Bs[c][r] = W[(col0 + r) * E_ + k0 + c];
        }
        __syncthreads();
        #pragma unroll
        for (int k = 0; k < 16; k++) {
            float a0 = As[k][r0], a1 = As[k][r0+1], a2 = As[k][r0+2], a3 = As[k][r0+3];
            float b0 = Bs[k][c0], b1 = Bs[k][c0+1], b2 = Bs[k][c0+2], b3 = Bs[k][c0+3];
            acc[0][0] += a0*b0; acc[0][1] += a0*b1; acc[0][2] += a0*b2; acc[0][3] += a0*b3;
            acc[1][0] += a1*b0; acc[1][1] += a1*b1; acc[1][2] += a1*b2; acc[1][3] += a1*b3;
            acc[2][0] += a2*b0; acc[2][1] += a2*b1; acc[2][2] += a2*b2; acc[2][3] += a2*b3;
            acc[3][0] += a3*b0; acc[3][1] += a3*b1; acc[3][2] += a3*b2; acc[3][3] += a3*b3;
        }
        __syncthreads();
    }
    #pragma unroll
    for (int i = 0; i < 4; i++) {
        int r = row0 + r0 + i;
        #pragma unroll
        for (int j = 0; j < 4; j++) {
            int f = col0 + c0 + j;
            out[(size_t)r * E_ + f] = acc[i][j] + bias[f];
        }
    }
}

// ---------------- launch ----------------
extern "C" void kernel_launch(void* const* d_in, const int* in_sizes, int n_in,
                              void* d_out, int out_size) {
    const float* fwd  = (const float*)d_in[0];
    const float* bwd  = (const float*)d_in[1];
    const int*   kpm  = (const int*)d_in[2];
    const float* W    = (const float*)d_in[3];   // (3E, E)
    const float* bias = (const float*)d_in[4];   // (3E,)
    const float* outw = (const float*)d_in[5];   // (E, E)
    const float* outb = (const float*)d_in[6];   // (E,)
    float* out = (float*)d_out;                       // (T,B,E)
    float* avg = out + (size_t)T_ * B_ * E_;          // (B,T,S)

    build_qin_kernel<<<(T_ * B_ * E_) / 256, 256>>>(fwd, bwd);
    proj_q_kernel<<<dim3(E_ / 64, (T_ * B_) / 64), 256>>>(W, bias);
    proj_kv_kernel<<<dim3((2 * E_) / 64, (S_ * B_) / 64), 256>>>(fwd, bwd, W, bias);
    scores_kernel<<<dim3(S_ / 64, T_ / 64, B_ * H_), 256>>>(kpm);
    softmax_avg_kernel<<<B_ * T_, 256>>>(avg);
    attn_kernel<<<dim3(1, T_ / 64, B_ * H_), 256>>>();
    out_proj_kernel<<<dim3(E_ / 64, (T_ * B_) / 64), 256>>>(outw, outb, out);
}

// round 9
// speedup vs baseline: 1.4963x; 1.4963x over previous
#include <cuda_runtime.h>
#include <math.h>

#define T_ 1024
#define B_ 8
#define E_ 512
#define H_ 8
#define D_ 64
#define S_ 2048

// ---------------- scratch (device globals; no allocations) ----------------
__device__ float g_qin[T_ * B_ * E_];                 // (t,b,e)
__device__ float g_q[B_ * H_ * T_ * D_];              // (b,h,t,d)
__device__ float g_k[B_ * H_ * S_ * D_];              // (b,h,s,d)
__device__ float g_v[B_ * H_ * S_ * D_];              // (b,h,s,d)
__device__ float g_p[(size_t)B_ * H_ * T_ * S_];      // (b,h,t,s) raw scores -> probs
__device__ float g_attn[T_ * B_ * E_];                // (t,b, h*64+d)

// ---------------- q_in = shift(fwd,+1) + shift(bwd,-1) ----------------
__global__ void build_qin_kernel(const float* __restrict__ fwd,
                                 const float* __restrict__ bwd) {
    int idx = blockIdx.x * blockDim.x + threadIdx.x;
    int tb = idx / E_;
    int t = tb / B_;
    float v = 0.f;
    if (t > 0)      v += fwd[idx - B_ * E_];
    if (t < T_ - 1) v += bwd[idx + B_ * E_];
    g_qin[idx] = v;
}

// ---------------- 128x128 tile mainloop: acc += A(128,K) * B(128,K)^T ----------------
// A, B pre-offset to tile origin; row-major with leading dims lda/ldb.
__device__ __forceinline__ void gemm128_loop(const float* __restrict__ A, int lda,
                                             const float* __restrict__ B, int ldb,
                                             int Kdim, float acc[8][8],
                                             float As[8][132], float Bs[8][132]) {
    const int tid = threadIdx.x;
    const int ar = tid >> 1;             // 0..127
    const int ah = (tid & 1) << 2;       // 0 or 4
    const int tr = (tid >> 4) << 3;      // 0..120
    const int tc = (tid & 15) << 3;      // 0..120
    for (int k0 = 0; k0 < Kdim; k0 += 8) {
        float4 av = *(const float4*)(A + (size_t)ar * lda + k0 + ah);
        float4 bv = *(const float4*)(B + (size_t)ar * ldb + k0 + ah);
        As[ah+0][ar] = av.x; As[ah+1][ar] = av.y; As[ah+2][ar] = av.z; As[ah+3][ar] = av.w;
        Bs[ah+0][ar] = bv.x; Bs[ah+1][ar] = bv.y; Bs[ah+2][ar] = bv.z; Bs[ah+3][ar] = bv.w;
        __syncthreads();
        #pragma unroll
        for (int k = 0; k < 8; k++) {
            float ra[8], rb[8];
            *(float4*)(ra)     = *(const float4*)&As[k][tr];
            *(float4*)(ra + 4) = *(const float4*)&As[k][tr + 4];
            *(float4*)(rb)     = *(const float4*)&Bs[k][tc];
            *(float4*)(rb + 4) = *(const float4*)&Bs[k][tc + 4];
            #pragma unroll
            for (int i = 0; i < 8; i++)
                #pragma unroll
                for (int j = 0; j < 8; j++)
                    acc[i][j] += ra[i] * rb[j];
        }
        __syncthreads();
    }
}

// ---------------- proj_q: g_q = qin @ Wq^T + bq, scattered to (b,h,t,d) ----------------
__global__ void proj_q_kernel(const float* __restrict__ W,
                              const float* __restrict__ bias) {
    __shared__ float As[8][132], Bs[8][132];
    const int row0 = blockIdx.y * 128;   // (t*B+b) rows, M=8192
    const int col0 = blockIdx.x * 128;   // f in [0,512)
    float acc[8][8] = {};
    gemm128_loop(g_qin + (size_t)row0 * E_, E_,
                 W + (size_t)col0 * E_, E_, E_, acc, As, Bs);
    const int tr = (threadIdx.x >> 4) << 3, tc = (threadIdx.x & 15) << 3;
    const int f0 = col0 + tc;
    const int h = f0 >> 6, d0 = f0 & 63;
    float b0 = bias[f0+0], b1 = bias[f0+1], b2 = bias[f0+2], b3 = bias[f0+3];
    float b4 = bias[f0+4], b5 = bias[f0+5], b6 = bias[f0+6], b7 = bias[f0+7];
    #pragma unroll
    for (int i = 0; i < 8; i++) {
        int r = row0 + tr + i;
        int t = r >> 3, b = r & 7;
        float* dst = &g_q[(size_t)(((b << 3) + h) * T_ + t) * D_ + d0];
        *(float4*)dst       = make_float4(acc[i][0]+b0, acc[i][1]+b1, acc[i][2]+b2, acc[i][3]+b3);
        *(float4*)(dst + 4) = make_float4(acc[i][4]+b4, acc[i][5]+b5, acc[i][6]+b6, acc[i][7]+b7);
    }
}

// ---------------- proj_kv: K/V = kv_in @ W^T + b, scattered to (b,h,s,d) ----------------
__global__ void proj_kv_kernel(const float* __restrict__ fwd,
                               const float* __restrict__ bwd,
                               const float* __restrict__ W,
                               const float* __restrict__ bias) {
    __shared__ float As[8][132], Bs[8][132];
    const int row0 = blockIdx.y * 128;   // kv_in rows (s*B+b), M=16384
    const int col0 = blockIdx.x * 128;   // f in [0,1024): K then V
    const float* Asrc = (row0 < T_ * B_) ? (fwd + (size_t)row0 * E_)
                                         : (bwd + (size_t)(row0 - T_ * B_) * E_);
    float acc[8][8] = {};
    gemm128_loop(Asrc, E_, W + (size_t)(E_ + col0) * E_, E_, E_, acc, As, Bs);
    const int tr = (threadIdx.x >> 4) << 3, tc = (threadIdx.x & 15) << 3;
    const int fl = col0 + tc;            // 0..1016, multiple of 8
    float bb[8];
    #pragma unroll
    for (int j = 0; j < 8; j++) bb[j] = bias[E_ + fl + j];
    #pragma unroll
    for (int i = 0; i < 8; i++) {
        int r = row0 + tr + i;
        int s = r >> 3, b = r & 7;
        float* dst;
        if (fl < E_) {
            int h = fl >> 6, d = fl & 63;
            dst = &g_k[((size_t)((b << 3) + h) * S_ + s) * D_ + d];
        } else {
            int f2 = fl - E_;
            int h = f2 >> 6, d = f2 & 63;
            dst = &g_v[((size_t)((b << 3) + h) * S_ + s) * D_ + d];
        }
        *(float4*)dst       = make_float4(acc[i][0]+bb[0], acc[i][1]+bb[1], acc[i][2]+bb[2], acc[i][3]+bb[3]);
        *(float4*)(dst + 4) = make_float4(acc[i][4]+bb[4], acc[i][5]+bb[5], acc[i][6]+bb[6], acc[i][7]+bb[7]);
    }
}

// ---------------- scores: raw q.k, NO masking (softmax applies mask) ----------------
// Skip tiles that are entirely inside the disallowed band t <= s <= t+T.
__global__ void scores_kernel() {
    const int bh = blockIdx.z;
    const int t0 = blockIdx.y * 128;
    const int s0 = blockIdx.x * 128;
    if (s0 >= t0 + 128 && s0 <= t0 + 896) return;   // fully masked tile
    __shared__ float As[8][132], Bs[8][132];
    float acc[8][8] = {};
    gemm128_loop(g_q + (size_t)bh * T_ * D_ + (size_t)t0 * D_, D_,
                 g_k + (size_t)bh * S_ * D_ + (size_t)s0 * D_, D_, D_, acc, As, Bs);
    float* P = g_p + (size_t)bh * T_ * S_;
    const int tr = (threadIdx.x >> 4) << 3, tc = (threadIdx.x & 15) << 3;
    #pragma unroll
    for (int i = 0; i < 8; i++) {
        size_t off = (size_t)(t0 + tr + i) * S_ + s0 + tc;
        *(float4*)&P[off]     = make_float4(acc[i][0], acc[i][1], acc[i][2], acc[i][3]);
        *(float4*)&P[off + 4] = make_float4(acc[i][4], acc[i][5], acc[i][6], acc[i][7]);
    }
}

// ---------------- softmax per (b,t) over all heads + head-mean; mask applied here ----------------
__device__ __forceinline__ float blk_reduce(float v, bool is_max, float* red) {
    #pragma unroll
    for (int o = 16; o; o >>= 1) {
        float w = __shfl_xor_sync(0xffffffffu, v, o);
        v = is_max ? fmaxf(v, w) : v + w;
    }
    if ((threadIdx.x & 31) == 0) red[threadIdx.x >> 5] = v;
    __syncthreads();
    if (threadIdx.x < 32) {
        float x = (threadIdx.x < 8) ? red[threadIdx.x] : (is_max ? -1e30f : 0.f);
        #pragma unroll
        for (int o = 4; o; o >>= 1) {
            float w = __shfl_xor_sync(0xffffffffu, x, o);
            x = is_max ? fmaxf(x, w) : x + w;
        }
        if (threadIdx.x == 0) red[0] = x;
    }
    __syncthreads();
    float r = red[0];
    __syncthreads();
    return r;
}

__global__ void softmax_avg_kernel(const int* __restrict__ kpm,
                                   float* __restrict__ avg_out) {
    __shared__ float red[32];
    const int bt = blockIdx.x;            // b*T + t
    const int b = bt >> 10;
    const int t = bt & (T_ - 1);
    const int tid = threadIdx.x;
    bool msk[8];
    #pragma unroll
    for (int i = 0; i < 8; i++) {
        int s = tid + (i << 8);
        msk[i] = (s >= t && s <= t + T_) || (kpm[b * T_ + (s & (T_ - 1))] != 0);
    }
    float avg[8] = {};
    for (int h = 0; h < H_; h++) {
        float* row = g_p + ((size_t)(((b << 3) + h) * T_ + t)) * S_;
        float vreg[8];
        float m = -1e30f;
        #pragma unroll
        for (int i = 0; i < 8; i++) {
            int s = tid + (i << 8);
            float v = msk[i] ? -1e30f : row[s];
            vreg[i] = v;
            m = fmaxf(m, v);
        }
        m = blk_reduce(m, true, red);
        float sum = 0.f;
        #pragma unroll
        for (int i = 0; i < 8; i++) {
            if (!msk[i]) { vreg[i] = __expf(vreg[i] - m); sum += vreg[i]; }
            else vreg[i] = 0.f;
        }
        sum = blk_reduce(sum, false, red);
        float inv = 1.f / sum;
        #pragma unroll
        for (int i = 0; i < 8; i++) {
            float p = vreg[i] * inv;
            row[tid + (i << 8)] = p;
            avg[i] += p;
        }
    }
    size_t o = (size_t)bt * S_;
    #pragma unroll
    for (int i = 0; i < 8; i++)
        avg_out[o + tid + (i << 8)] = avg[i] * (1.f / (float)H_);
}

// ---------------- attn = p @ v  (BM=128, BN=64, BK=16; skip zero k-tiles) ----------------
__global__ void attn_kernel() {
    __shared__ float Ps[16][132];
    __shared__ float Vs[16][64];
    const int t0 = blockIdx.x * 128;
    const int bh = blockIdx.y;
    const float* P = g_p + (size_t)bh * T_ * S_ + (size_t)t0 * S_;
    const float* V = g_v + (size_t)bh * S_ * D_;
    const int tid = threadIdx.x;
    const int tr = (tid >> 4) << 3;      // 0..120
    const int tc = (tid & 15) << 2;      // 0..60
    const int pr = tid >> 1;             // 0..127 P row
    const int pc0 = ((tid & 1) << 3);    // 0 or 8 (this thread loads c and c+4)
    const int vk = tid >> 4, vn = (tid & 15) << 2;
    float acc[8][4] = {};
    for (int k0 = 0; k0 < S_; k0 += 16) {
        if (k0 >= t0 + 128 && k0 + 15 <= t0 + T_) continue;  // p exactly 0 here
        {
            float4 a0 = *(const float4*)(P + (size_t)pr * S_ + k0 + pc0);
            float4 a1 = *(const float4*)(P + (size_t)pr * S_ + k0 + pc0 + 4);
            Ps[pc0+0][pr] = a0.x; Ps[pc0+1][pr] = a0.y; Ps[pc0+2][pr] = a0.z; Ps[pc0+3][pr] = a0.w;
            Ps[pc0+4][pr] = a1.x; Ps[pc0+5][pr] = a1.y; Ps[pc0+6][pr] = a1.z; Ps[pc0+7][pr] = a1.w;
        }
        *(float4*)&Vs[vk][vn] = *(const float4*)(V + (size_t)(k0 + vk) * D_ + vn);
        __syncthreads();
        #pragma unroll
        for (int k = 0; k < 16; k++) {
            float ra[8], rb[4];
            *(float4*)(ra)     = *(const float4*)&Ps[k][tr];
            *(float4*)(ra + 4) = *(const float4*)&Ps[k][tr + 4];
            *(float4*)(rb)     = *(const float4*)&Vs[k][tc];
            #pragma unroll
            for (int i = 0; i < 8; i++)
                #pragma unroll
                for (int j = 0; j < 4; j++)
                    acc[i][j] += ra[i] * rb[j];
        }
        __syncthreads();
    }
    const int b = bh >> 3, h = bh & 7;
    #pragma unroll
    for (int i = 0; i < 8; i++) {
        int t = t0 + tr + i;
        *(float4*)&g_attn[(size_t)((t << 3) + b) * E_ + (h << 6) + tc] =
            make_float4(acc[i][0], acc[i][1], acc[i][2], acc[i][3]);
    }
}

// ---------------- out = attn @ out_w^T + out_b ----------------
__global__ void out_proj_kernel(const float* __restrict__ W,
                                const float* __restrict__ bias,
                                float* __restrict__ out) {
    __shared__ float As[8][132], Bs[8][132];
    const int row0 = blockIdx.y * 128;
    const int col0 = blockIdx.x * 128;
    float acc[8][8] = {};
    gemm128_loop(g_attn + (size_t)row0 * E_, E_,
                 W + (size_t)col0 * E_, E_, E_, acc, As, Bs);
    const int tr = (threadIdx.x >> 4) << 3, tc = (threadIdx.x & 15) << 3;
    const int f0 = col0 + tc;
    float bb[8];
    #pragma unroll
    for (int j = 0; j < 8; j++) bb[j] = bias[f0 + j];
    #pragma unroll
    for (int i = 0; i < 8; i++) {
        int r = row0 + tr + i;
        float* dst = &out[(size_t)r * E_ + f0];
        *(float4*)dst       = make_float4(acc[i][0]+bb[0], acc[i][1]+bb[1], acc[i][2]+bb[2], acc[i][3]+bb[3]);
        *(float4*)(dst + 4) = make_float4(acc[i][4]+bb[4], acc[i][5]+bb[5], acc[i][6]+bb[6], acc[i][7]+bb[7]);
    }
}

// ---------------- launch ----------------
extern "C" void kernel_launch(void* const* d_in, const int* in_sizes, int n_in,
                              void* d_out, int out_size) {
    const float* fwd  = (const float*)d_in[0];
    const float* bwd  = (const float*)d_in[1];
    const int*   kpm  = (const int*)d_in[2];
    const float* W    = (const float*)d_in[3];   // (3E, E)
    const float* bias = (const float*)d_in[4];   // (3E,)
    const float* outw = (const float*)d_in[5];   // (E, E)
    const float* outb = (const float*)d_in[6];   // (E,)
    float* out = (float*)d_out;                       // (T,B,E)
    float* avg = out + (size_t)T_ * B_ * E_;          // (B,T,S)

    build_qin_kernel<<<(T_ * B_ * E_) / 256, 256>>>(fwd, bwd);
    proj_q_kernel<<<dim3(E_ / 128, (T_ * B_) / 128), 256>>>(W, bias);
    proj_kv_kernel<<<dim3((2 * E_) / 128, (S_ * B_) / 128), 256>>>(fwd, bwd, W, bias);
    scores_kernel<<<dim3(S_ / 128, T_ / 128, B_ * H_), 256>>>();
    softmax_avg_kernel<<<B_ * T_, 256>>>(kpm, avg);
    attn_kernel<<<dim3(T_ / 128, B_ * H_), 256>>>();
    out_proj_kernel<<<dim3(E_ / 128, (T_ * B_) / 128), 256>>>(outw, outb, out);
}

// round 11
// speedup vs baseline: 2.1127x; 1.4119x over previous
#include <cuda_runtime.h>
#include <math.h>
#include <stdint.h>

#define T_ 1024
#define B_ 8
#define E_ 512
#define H_ 8
#define D_ 64
#define S_ 2048
#define LDK 20
#define LDV 72

// ---------------- scratch (device globals; no allocations) ----------------
__device__ float g_qin[T_ * B_ * E_];                 // (t,b,e)
__device__ float g_q[B_ * H_ * T_ * D_];              // (b,h,t,d)
__device__ float g_k[B_ * H_ * S_ * D_];              // (b,h,s,d)
__device__ float g_v[B_ * H_ * S_ * D_];              // (b,h,s,d)
__device__ float g_p[(size_t)B_ * H_ * T_ * S_];      // (b,h,t,s)
__device__ float g_attn[T_ * B_ * E_];                // (t,b, h*64+d)

// ---------------- tf32 helpers ----------------
__device__ __forceinline__ uint32_t f2tf32(float x) {
    uint32_t r;
    asm("cvt.rna.tf32.f32 %0, %1;" : "=r"(r) : "f"(x));
    return r;
}

__device__ __forceinline__ void mma8(float c[4],
                                     uint32_t a0, uint32_t a1, uint32_t a2, uint32_t a3,
                                     uint32_t b0, uint32_t b1) {
    asm volatile(
        "mma.sync.aligned.m16n8k8.row.col.f32.tf32.tf32.f32 "
        "{%0,%1,%2,%3},{%4,%5,%6,%7},{%8,%9},{%0,%1,%2,%3};"
        : "+f"(c[0]), "+f"(c[1]), "+f"(c[2]), "+f"(c[3])
        : "r"(a0), "r"(a1), "r"(a2), "r"(a3), "r"(b0), "r"(b1));
}

// ---------------- staging: 128 rows x 16 cols fp32 -> smem tf32 (hi[,lo]) ----------------
__device__ __forceinline__ void stage3(const float* __restrict__ src, int ld,
                                       float (*dh)[LDK], float (*dl)[LDK]) {
    int r = threadIdx.x >> 1, c = (threadIdx.x & 1) << 3;
    const float* p = src + (size_t)r * ld + c;
    float4 v0 = *(const float4*)p;
    float4 v1 = *(const float4*)(p + 4);
    float v[8] = {v0.x, v0.y, v0.z, v0.w, v1.x, v1.y, v1.z, v1.w};
    float h[8], l[8];
    #pragma unroll
    for (int i = 0; i < 8; i++) {
        h[i] = __uint_as_float(f2tf32(v[i]));
        l[i] = __uint_as_float(f2tf32(v[i] - h[i]));
    }
    *(float4*)&dh[r][c]     = make_float4(h[0], h[1], h[2], h[3]);
    *(float4*)&dh[r][c + 4] = make_float4(h[4], h[5], h[6], h[7]);
    *(float4*)&dl[r][c]     = make_float4(l[0], l[1], l[2], l[3]);
    *(float4*)&dl[r][c + 4] = make_float4(l[4], l[5], l[6], l[7]);
}

__device__ __forceinline__ void stage1(const float* __restrict__ src, int ld,
                                       float (*dh)[LDK]) {
    int r = threadIdx.x >> 1, c = (threadIdx.x & 1) << 3;
    const float* p = src + (size_t)r * ld + c;
    float4 v0 = *(const float4*)p;
    float4 v1 = *(const float4*)(p + 4);
    float v[8] = {v0.x, v0.y, v0.z, v0.w, v1.x, v1.y, v1.z, v1.w};
    float h[8];
    #pragma unroll
    for (int i = 0; i < 8; i++) h[i] = __uint_as_float(f2tf32(v[i]));
    *(float4*)&dh[r][c]     = make_float4(h[0], h[1], h[2], h[3]);
    *(float4*)&dh[r][c + 4] = make_float4(h[4], h[5], h[6], h[7]);
}

// ---------------- 128x128 block: acc += A(128x16) * B(128x16)^T, 3xTF32 ----------------
__device__ __forceinline__ void mma_block3(float (*Ah)[LDK], float (*Al)[LDK],
                                           float (*Bh)[LDK], float (*Bl)[LDK],
                                           float acc[4][4][4]) {
    const int lane = threadIdx.x & 31, warp = threadIdx.x >> 5;
    const int wm = warp >> 2, wn = warp & 3;
    const int gid = lane >> 2, t4 = lane & 3;
    #pragma unroll
    for (int kk = 0; kk < 16; kk += 8) {
        uint32_t ah[4][4], al[4][4];
        #pragma unroll
        for (int mi = 0; mi < 4; mi++) {
            int r = wm * 64 + mi * 16 + gid;
            ah[mi][0] = __float_as_uint(Ah[r][kk + t4]);
            ah[mi][1] = __float_as_uint(Ah[r + 8][kk + t4]);
            ah[mi][2] = __float_as_uint(Ah[r][kk + t4 + 4]);
            ah[mi][3] = __float_as_uint(Ah[r + 8][kk + t4 + 4]);
            al[mi][0] = __float_as_uint(Al[r][kk + t4]);
            al[mi][1] = __float_as_uint(Al[r + 8][kk + t4]);
            al[mi][2] = __float_as_uint(Al[r][kk + t4 + 4]);
            al[mi][3] = __float_as_uint(Al[r + 8][kk + t4 + 4]);
        }
        #pragma unroll
        for (int ni = 0; ni < 4; ni++) {
            int c = wn * 32 + ni * 8 + gid;
            uint32_t bh0 = __float_as_uint(Bh[c][kk + t4]);
            uint32_t bh1 = __float_as_uint(Bh[c][kk + t4 + 4]);
            uint32_t bl0 = __float_as_uint(Bl[c][kk + t4]);
            uint32_t bl1 = __float_as_uint(Bl[c][kk + t4 + 4]);
            #pragma unroll
            for (int mi = 0; mi < 4; mi++) {
                mma8(acc[mi][ni], ah[mi][0], ah[mi][1], ah[mi][2], ah[mi][3], bh0, bh1);
                mma8(acc[mi][ni], ah[mi][0], ah[mi][1], ah[mi][2], ah[mi][3], bl0, bl1);
                mma8(acc[mi][ni], al[mi][0], al[mi][1], al[mi][2], al[mi][3], bh0, bh1);
            }
        }
    }
}

// 1-pass version
__device__ __forceinline__ void mma_block1(float (*Ah)[LDK], float (*Bh)[LDK],
                                           float acc[4][4][4]) {
    const int lane = threadIdx.x & 31, warp = threadIdx.x >> 5;
    const int wm = warp >> 2, wn = warp & 3;
    const int gid = lane >> 2, t4 = lane & 3;
    #pragma unroll
    for (int kk = 0; kk < 16; kk += 8) {
        uint32_t ah[4][4];
        #pragma unroll
        for (int mi = 0; mi < 4; mi++) {
            int r = wm * 64 + mi * 16 + gid;
            ah[mi][0] = __float_as_uint(Ah[r][kk + t4]);
            ah[mi][1] = __float_as_uint(Ah[r + 8][kk + t4]);
            ah[mi][2] = __float_as_uint(Ah[r][kk + t4 + 4]);
            ah[mi][3] = __float_as_uint(Ah[r + 8][kk + t4 + 4]);
        }
        #pragma unroll
        for (int ni = 0; ni < 4; ni++) {
            int c = wn * 32 + ni * 8 + gid;
            uint32_t bh0 = __float_as_uint(Bh[c][kk + t4]);
            uint32_t bh1 = __float_as_uint(Bh[c][kk + t4 + 4]);
            #pragma unroll
            for (int mi = 0; mi < 4; mi++)
                mma8(acc[mi][ni], ah[mi][0], ah[mi][1], ah[mi][2], ah[mi][3], bh0, bh1);
        }
    }
}

// ---------------- q_in = shift(fwd,+1) + shift(bwd,-1) ----------------
__global__ void build_qin_kernel(const float* __restrict__ fwd,
                                 const float* __restrict__ bwd) {
    int idx = blockIdx.x * blockDim.x + threadIdx.x;
    int tb = idx / E_;
    int t = tb / B_;
    float v = 0.f;
    if (t > 0)      v += fwd[idx - B_ * E_];
    if (t < T_ - 1) v += bwd[idx + B_ * E_];
    g_qin[idx] = v;
}

// ---------------- proj_q: g_q = qin @ Wq^T + bq -> (b,h,t,d) ----------------
__global__ __launch_bounds__(256) void proj_q_kernel(const float* __restrict__ W,
                                                     const float* __restrict__ bias) {
    __shared__ float Ah[128][LDK], Al[128][LDK], Bh[128][LDK], Bl[128][LDK];
    const int row0 = blockIdx.y * 128;
    const int col0 = blockIdx.x * 128;
    const float* A = g_qin + (size_t)row0 * E_;
    const float* Bw = W + (size_t)col0 * E_;
    float acc[4][4][4] = {};
    for (int k0 = 0; k0 < E_; k0 += 16) {
        stage3(A + k0, E_, Ah, Al);
        stage3(Bw + k0, E_, Bh, Bl);
        __syncthreads();
        mma_block3(Ah, Al, Bh, Bl, acc);
        __syncthreads();
    }
    const int lane = threadIdx.x & 31, warp = threadIdx.x >> 5;
    const int wm = warp >> 2, wn = warp & 3;
    const int gid = lane >> 2, t4 = lane & 3;
    #pragma unroll
    for (int mi = 0; mi < 4; mi++) {
        #pragma unroll
        for (int ni = 0; ni < 4; ni++) {
            int r = row0 + wm * 64 + mi * 16 + gid;
            int f = col0 + wn * 32 + ni * 8 + 2 * t4;
            int h = f >> 6, d = f & 63;
            float bb0 = bias[f], bb1 = bias[f + 1];
            int t = r >> 3, b = r & 7;
            *(float2*)&g_q[(size_t)(((b << 3) + h) * T_ + t) * D_ + d] =
                make_float2(acc[mi][ni][0] + bb0, acc[mi][ni][1] + bb1);
            *(float2*)&g_q[(size_t)(((b << 3) + h) * T_ + t + 1) * D_ + d] =
                make_float2(acc[mi][ni][2] + bb0, acc[mi][ni][3] + bb1);
        }
    }
}

// ---------------- proj_kv -> g_k / g_v (b,h,s,d) ----------------
__global__ __launch_bounds__(256) void proj_kv_kernel(const float* __restrict__ fwd,
                                                      const float* __restrict__ bwd,
                                                      const float* __restrict__ W,
                                                      const float* __restrict__ bias) {
    __shared__ float Ah[128][LDK], Al[128][LDK], Bh[128][LDK], Bl[128][LDK];
    const int row0 = blockIdx.y * 128;   // kv_in rows (s*B+b)
    const int col0 = blockIdx.x * 128;   // f in [0,1024)
    const float* A = (row0 < T_ * B_) ? (fwd + (size_t)row0 * E_)
                                      : (bwd + (size_t)(row0 - T_ * B_) * E_);
    const float* Bw = W + (size_t)(E_ + col0) * E_;
    float acc[4][4][4] = {};
    for (int k0 = 0; k0 < E_; k0 += 16) {
        stage3(A + k0, E_, Ah, Al);
        stage3(Bw + k0, E_, Bh, Bl);
        __syncthreads();
        mma_block3(Ah, Al, Bh, Bl, acc);
        __syncthreads();
    }
    const int lane = threadIdx.x & 31, warp = threadIdx.x >> 5;
    const int wm = warp >> 2, wn = warp & 3;
    const int gid = lane >> 2, t4 = lane & 3;
    float* dstbase = (col0 < E_) ? g_k : g_v;
    #pragma unroll
    for (int mi = 0; mi < 4; mi++) {
        #pragma unroll
        for (int ni = 0; ni < 4; ni++) {
            int r = row0 + wm * 64 + mi * 16 + gid;
            int f = col0 + wn * 32 + ni * 8 + 2 * t4;
            float bb0 = bias[E_ + f], bb1 = bias[E_ + f + 1];
            int f2 = f & (E_ - 1);
            int h = f2 >> 6, d = f2 & 63;
            int s = r >> 3, b = r & 7;
            *(float2*)&dstbase[((size_t)((b << 3) + h) * S_ + s) * D_ + d] =
                make_float2(acc[mi][ni][0] + bb0, acc[mi][ni][1] + bb1);
            *(float2*)&dstbase[((size_t)((b << 3) + h) * S_ + s + 1) * D_ + d] =
                make_float2(acc[mi][ni][2] + bb0, acc[mi][ni][3] + bb1);
        }
    }
}

// ---------------- scores: raw q.k (3xTF32); skip fully-masked tiles ----------------
__global__ __launch_bounds__(256) void scores_kernel() {
    const int bh = blockIdx.z;
    const int t0 = blockIdx.y * 128;
    const int s0 = blockIdx.x * 128;
    if (s0 >= t0 + 128 && s0 <= t0 + 896) return;
    __shared__ float Ah[128][LDK], Al[128][LDK], Bh[128][LDK], Bl[128][LDK];
    const float* Q = g_q + (size_t)bh * T_ * D_ + (size_t)t0 * D_;
    const float* K = g_k + (size_t)bh * S_ * D_ + (size_t)s0 * D_;
    float acc[4][4][4] = {};
    for (int k0 = 0; k0 < D_; k0 += 16) {
        stage3(Q + k0, D_, Ah, Al);
        stage3(K + k0, D_, Bh, Bl);
        __syncthreads();
        mma_block3(Ah, Al, Bh, Bl, acc);
        __syncthreads();
    }
    float* P = g_p + (size_t)bh * T_ * S_;
    const int lane = threadIdx.x & 31, warp = threadIdx.x >> 5;
    const int wm = warp >> 2, wn = warp & 3;
    const int gid = lane >> 2, t4 = lane & 3;
    #pragma unroll
    for (int mi = 0; mi < 4; mi++) {
        #pragma unroll
        for (int ni = 0; ni < 4; ni++) {
            int r = t0 + wm * 64 + mi * 16 + gid;
            int c = s0 + wn * 32 + ni * 8 + 2 * t4;
            *(float2*)&P[(size_t)r * S_ + c] = make_float2(acc[mi][ni][0], acc[mi][ni][1]);
            *(float2*)&P[(size_t)(r + 8) * S_ + c] = make_float2(acc[mi][ni][2], acc[mi][ni][3]);
        }
    }
}

// ---------------- softmax per (b,t) over all heads + head-mean ----------------
__device__ __forceinline__ float blk_reduce(float v, bool is_max, float* red) {
    #pragma unroll
    for (int o = 16; o; o >>= 1) {
        float w = __shfl_xor_sync(0xffffffffu, v, o);
        v = is_max ? fmaxf(v, w) : v + w;
    }
    if ((threadIdx.x & 31) == 0) red[threadIdx.x >> 5] = v;
    __syncthreads();
    if (threadIdx.x < 32) {
        float x = (threadIdx.x < 8) ? red[threadIdx.x] : (is_max ? -1e30f : 0.f);
        #pragma unroll
        for (int o = 4; o; o >>= 1) {
            float w = __shfl_xor_sync(0xffffffffu, x, o);
            x = is_max ? fmaxf(x, w) : x + w;
        }
        if (threadIdx.x == 0) red[0] = x;
    }
    __syncthreads();
    float r = red[0];
    __syncthreads();
    return r;
}

__global__ void softmax_avg_kernel(const int* __restrict__ kpm,
                                   float* __restrict__ avg_out) {
    __shared__ float red[32];
    const int bt = blockIdx.x;
    const int b = bt >> 10;
    const int t = bt & (T_ - 1);
    const int tid = threadIdx.x;
    bool msk[8];
    #pragma unroll
    for (int i = 0; i < 8; i++) {
        int s = tid + (i << 8);
        msk[i] = (s >= t && s <= t + T_) || (kpm[b * T_ + (s & (T_ - 1))] != 0);
    }
    float avg[8] = {};
    for (int h = 0; h < H_; h++) {
        float* row = g_p + ((size_t)(((b << 3) + h) * T_ + t)) * S_;
        float vreg[8];
        float m = -1e30f;
        #pragma unroll
        for (int i = 0; i < 8; i++) {
            int s = tid + (i << 8);
            float v = msk[i] ? -1e30f : row[s];
            vreg[i] = v;
            m = fmaxf(m, v);
        }
        m = blk_reduce(m, true, red);
        float sum = 0.f;
        #pragma unroll
        for (int i = 0; i < 8; i++) {
            if (!msk[i]) { vreg[i] = __expf(vreg[i] - m); sum += vreg[i]; }
            else vreg[i] = 0.f;
        }
        sum = blk_reduce(sum, false, red);
        float inv = 1.f / sum;
        #pragma unroll
        for (int i = 0; i < 8; i++) {
            float p = vreg[i] * inv;
            row[tid + (i << 8)] = p;
            avg[i] += p;
        }
    }
    size_t o = (size_t)bt * S_;
    #pragma unroll
    for (int i = 0; i < 8; i++)
        avg_out[o + tid + (i << 8)] = avg[i] * (1.f / (float)H_);
}

// ---------------- attn = p @ v (1-pass tf32, BM=128 BN=64, skip zero tiles) ----------------
__global__ __launch_bounds__(256) void attn_kernel() {
    __shared__ float Ph[128][LDK];
    __shared__ float Vh[16][LDV];
    const int t0 = blockIdx.x * 128;
    const int bh = blockIdx.y;
    const float* P = g_p + (size_t)bh * T_ * S_ + (size_t)t0 * S_;
    const float* V = g_v + (size_t)bh * S_ * D_;
    const int tid = threadIdx.x;
    const int lane = tid & 31, warp = tid >> 5;
    const int wm = warp >> 1, wn = warp & 1;   // warp tile: 32(t) x 32(d)
    const int gid = lane >> 2, t4 = lane & 3;
    float acc[2][4][4] = {};
    for (int k0 = 0; k0 < S_; k0 += 16) {
        if (k0 >= t0 + 128 && k0 + 15 <= t0 + T_) continue;  // p exactly 0 here
        stage1(P + k0, S_, Ph);
        {   // stage V 16x64 -> Vh[k][n]
            int r = tid >> 4, c = (tid & 15) << 2;
            float4 v = *(const float4*)(V + (size_t)(k0 + r) * D_ + c);
            float4 hv = make_float4(__uint_as_float(f2tf32(v.x)), __uint_as_float(f2tf32(v.y)),
                                    __uint_as_float(f2tf32(v.z)), __uint_as_float(f2tf32(v.w)));
            *(float4*)&Vh[r][c] = hv;
        }
        __syncthreads();
        #pragma unroll
        for (int kk = 0; kk < 16; kk += 8) {
            uint32_t ah[2][4];
            #pragma unroll
            for (int mi = 0; mi < 2; mi++) {
                int r = wm * 32 + mi * 16 + gid;
                ah[mi][0] = __float_as_uint(Ph[r][kk + t4]);
                ah[mi][1] = __float_as_uint(Ph[r + 8][kk + t4]);
                ah[mi][2] = __float_as_uint(Ph[r][kk + t4 + 4]);
                ah[mi][3] = __float_as_uint(Ph[r + 8][kk + t4 + 4]);
            }
            #pragma unroll
            for (int ni = 0; ni < 4; ni++) {
                int c = wn * 32 + ni * 8 + gid;
                uint32_t b0 = __float_as_uint(Vh[kk + t4][c]);
                uint32_t b1 = __float_as_uint(Vh[kk + t4 + 4][c]);
                #pragma unroll
                for (int mi = 0; mi < 2; mi++)
                    mma8(acc[mi][ni], ah[mi][0], ah[mi][1], ah[mi][2], ah[mi][3], b0, b1);
            }
        }
        __syncthreads();
    }
    const int b = bh >> 3, h = bh & 7;
    #pragma unroll
    for (int mi = 0; mi < 2; mi++) {
        #pragma unroll
        for (int ni = 0; ni < 4; ni++) {
            int t = t0 + wm * 32 + mi * 16 + gid;
            int d = wn * 32 + ni * 8 + 2 * t4;
            *(float2*)&g_attn[(size_t)((t << 3) + b) * E_ + (h << 6) + d] =
                make_float2(acc[mi][ni][0], acc[mi][ni][1]);
            *(float2*)&g_attn[(size_t)(((t + 8) << 3) + b) * E_ + (h << 6) + d] =
                make_float2(acc[mi][ni][2], acc[mi][ni][3]);
        }
    }
}

// ---------------- out = attn @ out_w^T + out_b (1-pass tf32) ----------------
__global__ __launch_bounds__(256) void out_proj_kernel(const float* __restrict__ W,
                                                       const float* __restrict__ bias,
                                                       float* __restrict__ out) {
    __shared__ float Ah[128][LDK], Bh[128][LDK];
    const int row0 = blockIdx.y * 128;
    const int col0 = blockIdx.x * 128;
    const float* A = g_attn + (size_t)row0 * E_;
    const float* Bw = W + (size_t)col0 * E_;
    float acc[4][4][4] = {};
    for (int k0 = 0; k0 < E_; k0 += 16) {
        stage1(A + k0, E_, Ah);
        stage1(Bw + k0, E_, Bh);
        __syncthreads();
        mma_block1(Ah, Bh, acc);
        __syncthreads();
    }
    const int lane = threadIdx.x & 31, warp = threadIdx.x >> 5;
    const int wm = warp >> 2, wn = warp & 3;
    const int gid = lane >> 2, t4 = lane & 3;
    #pragma unroll
    for (int mi = 0; mi < 4; mi++) {
        #pragma unroll
        for (int ni = 0; ni < 4; ni++) {
            int r = row0 + wm * 64 + mi * 16 + gid;
            int f = col0 + wn * 32 + ni * 8 + 2 * t4;
            float bb0 = bias[f], bb1 = bias[f + 1];
            *(float2*)&out[(size_t)r * E_ + f] =
                make_float2(acc[mi][ni][0] + bb0, acc[mi][ni][1] + bb1);
            *(float2*)&out[(size_t)(r + 8) * E_ + f] =
                make_float2(acc[mi][ni][2] + bb0, acc[mi][ni][3] + bb1);
        }
    }
}

// ---------------- launch ----------------
extern "C" void kernel_launch(void* const* d_in, const int* in_sizes, int n_in,
                              void* d_out, int out_size) {
    const float* fwd  = (const float*)d_in[0];
    const float* bwd  = (const float*)d_in[1];
    const int*   kpm  = (const int*)d_in[2];
    const float* W    = (const float*)d_in[3];   // (3E, E)
    const float* bias = (const float*)d_in[4];   // (3E,)
    const float* outw = (const float*)d_in[5];   // (E, E)
    const float* outb = (const float*)d_in[6];   // (E,)
    float* out = (float*)d_out;                       // (T,B,E)
    float* avg = out + (size_t)T_ * B_ * E_;          // (B,T,S)

    build_qin_kernel<<<(T_ * B_ * E_) / 256, 256>>>(fwd, bwd);
    proj_q_kernel<<<dim3(E_ / 128, (T_ * B_) / 128), 256>>>(W, bias);
    proj_kv_kernel<<<dim3((2 * E_) / 128, (S_ * B_) / 128), 256>>>(fwd, bwd, W, bias);
    scores_kernel<<<dim3(S_ / 128, T_ / 128, B_ * H_), 256>>>();
    softmax_avg_kernel<<<B_ * T_, 256>>>(kpm, avg);
    attn_kernel<<<dim3(T_ / 128, B_ * H_), 256>>>();
    out_proj_kernel<<<dim3(E_ / 128, (T_ * B_) / 128), 256>>>(outw, outb, out);
}